// round 2
// baseline (speedup 1.0000x reference)
#include <cuda_runtime.h>
#include <cuda_bf16.h>
#include <math.h>

// ---------------------------------------------------------------------------
// Problem constants
//   DIM=128, HALF=64, K=8, hd=512, out_dim = 23*64 = 1472, B = 32768
//   Pipeline:
//     FCNN1(lower=x[:, :64])  -> params1 [B,64,23]
//     RQS(upper=x[:,64:], params1) -> upper', ld1
//     FCNN2(upper')           -> params2 [B,64,23]
//     RQS(lower, params2)     -> lower', ld2
//     out = [concat(lower', upper') (B*128 floats)] ++ [logdet (B floats)]
// ---------------------------------------------------------------------------

#define MAXB 32768
#define HD   512
#define PDIM 1472

// Scratch (device globals: allocation-free per harness rules)
__device__ float g_h1[(size_t)MAXB * HD];
__device__ float g_h2[(size_t)MAXB * HD];
__device__ float g_params[(size_t)MAXB * PDIM];
__device__ float g_up[(size_t)MAXB * 64];
__device__ float g_ld[MAXB];

// ---------------------------------------------------------------------------
// SGEMM  C[M,N] = A[M,K] (row-major, row stride lda) * B[K,N] + bias, opt SiLU
// Tile: BM=128, BN=64, BK=8; 256 threads; per-thread 8x4 microtile.
// Requires: M%128==0, N%64==0, K%8==0 (true for all 6 calls).
// ---------------------------------------------------------------------------
template <int ACT>
__global__ __launch_bounds__(256)
void sgemm_bias(const float* __restrict__ A, int lda,
                const float* __restrict__ B,
                const float* __restrict__ bias,
                float* __restrict__ C,
                int M, int N, int K)
{
    constexpr int BM = 128, BN = 64, BK = 8, TM = 8, TN = 4;
    __shared__ float As[BK][BM];
    __shared__ float Bs[BK][BN];

    const int tid = threadIdx.x;
    const int tx  = tid & 15;   // N direction (16 * TN=4 -> 64)
    const int ty  = tid >> 4;   // M direction (16 * TM=8 -> 128)
    const int m0  = blockIdx.y * BM;
    const int n0  = blockIdx.x * BN;

    // A tile loaders: 128 rows x 8 k -> 4 floats / thread (float4 along K)
    const int arow = tid >> 1;
    const int akq  = (tid & 1) * 4;
    // B tile loaders: 8 rows x 64 cols -> 2 floats / thread (float2 along N)
    const int brow = tid >> 5;
    const int bcol = (tid & 31) * 2;

    float acc[TM][TN];
#pragma unroll
    for (int i = 0; i < TM; i++)
#pragma unroll
        for (int j = 0; j < TN; j++) acc[i][j] = 0.f;

    for (int k0 = 0; k0 < K; k0 += BK) {
        float4 av = *reinterpret_cast<const float4*>(
            A + (size_t)(m0 + arow) * lda + (k0 + akq));
        As[akq + 0][arow] = av.x;
        As[akq + 1][arow] = av.y;
        As[akq + 2][arow] = av.z;
        As[akq + 3][arow] = av.w;

        float2 bv = *reinterpret_cast<const float2*>(
            B + (size_t)(k0 + brow) * N + (n0 + bcol));
        Bs[brow][bcol]     = bv.x;
        Bs[brow][bcol + 1] = bv.y;

        __syncthreads();

#pragma unroll
        for (int kk = 0; kk < BK; kk++) {
            float4 a0 = *reinterpret_cast<const float4*>(&As[kk][ty * TM]);
            float4 a1 = *reinterpret_cast<const float4*>(&As[kk][ty * TM + 4]);
            float4 bb = *reinterpret_cast<const float4*>(&Bs[kk][tx * TN]);
            float aa[TM] = {a0.x, a0.y, a0.z, a0.w, a1.x, a1.y, a1.z, a1.w};
            float bv4[TN] = {bb.x, bb.y, bb.z, bb.w};
#pragma unroll
            for (int i = 0; i < TM; i++)
#pragma unroll
                for (int j = 0; j < TN; j++)
                    acc[i][j] = fmaf(aa[i], bv4[j], acc[i][j]);
        }
        __syncthreads();
    }

    // Epilogue
    float4 bsv = *reinterpret_cast<const float4*>(bias + n0 + tx * TN);
    const float bcols[TN] = {bsv.x, bsv.y, bsv.z, bsv.w};
#pragma unroll
    for (int i = 0; i < TM; i++) {
        const int m = m0 + ty * TM + i;
        float4 c;
        float v0 = acc[i][0] + bcols[0];
        float v1 = acc[i][1] + bcols[1];
        float v2 = acc[i][2] + bcols[2];
        float v3 = acc[i][3] + bcols[3];
        if (ACT) {  // SiLU
            v0 = v0 / (1.f + __expf(-v0));
            v1 = v1 / (1.f + __expf(-v1));
            v2 = v2 / (1.f + __expf(-v2));
            v3 = v3 / (1.f + __expf(-v3));
        }
        c.x = v0; c.y = v1; c.z = v2; c.w = v3;
        *reinterpret_cast<float4*>(C + (size_t)m * N + n0 + tx * TN) = c;
    }
}

// ---------------------------------------------------------------------------
// Rational-quadratic spline transform + log-det reduction.
// One block per sample (64 threads = 64 transformed dims).
// phase 0: transform upper half of x; write to g_up AND dout[:,64:]; ld->g_ld
// phase 1: transform lower half of x; write to dout[:, :64];
//          dout[B*128 + b] = g_ld[b] + sum(ld)
// ---------------------------------------------------------------------------
__device__ __forceinline__ float softplusf(float v)
{
    return (v > 20.f) ? v : log1pf(expf(v));
}

__global__ __launch_bounds__(64)
void rqs_kernel(const float* __restrict__ x,       // [B,128]
                const float* __restrict__ params,  // [B,64,23]
                float* __restrict__ y_scratch,     // g_up (phase 0) / unused
                float* __restrict__ dout,
                float* __restrict__ ld_buf,
                int phase, int Bn)
{
    const int b = blockIdx.x;
    const int j = threadIdx.x;  // 0..63

    const float xv = x[(size_t)b * 128 + (phase == 0 ? 64 + j : j)];
    const float* p = params + (size_t)b * PDIM + j * 23;

    float W[8], H[8], D7[7];
#pragma unroll
    for (int i = 0; i < 8; i++) W[i] = p[i];
#pragma unroll
    for (int i = 0; i < 8; i++) H[i] = p[8 + i];
#pragma unroll
    for (int i = 0; i < 7; i++) D7[i] = p[16 + i];

    // widths = MIN_W + (1 - 8*MIN_W) * softmax(W)
    float mw = W[0];
#pragma unroll
    for (int i = 1; i < 8; i++) mw = fmaxf(mw, W[i]);
    float sw = 0.f;
#pragma unroll
    for (int i = 0; i < 8; i++) { W[i] = expf(W[i] - mw); sw += W[i]; }
    const float invw = 1.f / sw;

    float mh = H[0];
#pragma unroll
    for (int i = 1; i < 8; i++) mh = fmaxf(mh, H[i]);
    float sh = 0.f;
#pragma unroll
    for (int i = 0; i < 8; i++) { H[i] = expf(H[i] - mh); sh += H[i]; }
    const float invh = 1.f / sh;

    float cumw[9], cumh[9];
    cumw[0] = 0.f; cumh[0] = 0.f;
#pragma unroll
    for (int i = 0; i < 8; i++) {
        cumw[i + 1] = cumw[i] + (0.001f + 0.992f * W[i] * invw);
        cumh[i + 1] = cumh[i] + (0.001f + 0.992f * H[i] * invh);
    }
#pragma unroll
    for (int i = 0; i < 9; i++) {
        cumw[i] = 2.f * cumw[i] - 1.f;
        cumh[i] = 2.f * cumh[i] - 1.f;
    }
    cumw[0] = -1.f; cumw[8] = 1.f;
    cumh[0] = -1.f; cumh[8] = 1.f;

    // derivs: d[0]=d[8]=MIN_D+softplus(const)=1 (compute as reference does)
    float d[9];
    const float CST = logf(expf(1.0f - 0.001f) - 1.0f);
    const float dpad = 0.001f + softplusf(CST);
    d[0] = dpad; d[8] = dpad;
#pragma unroll
    for (int i = 0; i < 7; i++) d[i + 1] = 0.001f + softplusf(D7[i]);

    // bin index: sum(x >= locs) - 1, locs[8] = cumw[8] + 1e-6
    int idx = 0;
#pragma unroll
    for (int i = 0; i < 9; i++) {
        float loc = cumw[i] + ((i == 8) ? 1e-6f : 0.f);
        idx += (xv >= loc) ? 1 : 0;
    }
    idx -= 1;
    idx = max(0, min(7, idx));

    float icw = 0.f, iw = 1.f, ich = 0.f, ih = 1.f, d0 = 1.f, d1 = 1.f;
#pragma unroll
    for (int i = 0; i < 8; i++) {
        if (i == idx) {
            icw = cumw[i]; iw = cumw[i + 1] - cumw[i];
            ich = cumh[i]; ih = cumh[i + 1] - cumh[i];
            d0 = d[i]; d1 = d[i + 1];
        }
    }
    const float idel = ih / iw;
    const float th   = (xv - icw) / iw;
    const float omt  = 1.f - th;
    const float t1mt = th * omt;

    const float numer = ih * (idel * th * th + d0 * t1mt);
    const float den   = idel + (d0 + d1 - 2.f * idel) * t1mt;
    float out = ich + numer / den;

    const float dnum = idel * idel *
        (d1 * th * th + 2.f * idel * t1mt + d0 * omt * omt);
    float lad = logf(dnum) - 2.f * logf(den);

    const bool inside = (xv >= -1.f) && (xv <= 1.f);
    if (!inside) { out = xv; lad = 0.f; }

    if (phase == 0) {
        y_scratch[(size_t)b * 64 + j] = out;
        dout[(size_t)b * 128 + 64 + j] = out;
    } else {
        dout[(size_t)b * 128 + j] = out;
    }

    // reduce lad over 64 lanes (2 warps)
    float v = lad;
#pragma unroll
    for (int off = 16; off > 0; off >>= 1)
        v += __shfl_down_sync(0xffffffffu, v, off);
    __shared__ float sred[2];
    if ((j & 31) == 0) sred[j >> 5] = v;
    __syncthreads();
    if (j == 0) {
        const float tot = sred[0] + sred[1];
        if (phase == 0) ld_buf[b] = tot;
        else dout[(size_t)Bn * 128 + b] = ld_buf[b] + tot;
    }
}

// ---------------------------------------------------------------------------
// Launch
// ---------------------------------------------------------------------------
extern "C" void kernel_launch(void* const* d_in, const int* in_sizes, int n_in,
                              void* d_out, int out_size)
{
    const float* x     = (const float*)d_in[0];
    const float* f1w1  = (const float*)d_in[1];
    const float* f1b1  = (const float*)d_in[2];
    const float* f1w2  = (const float*)d_in[3];
    const float* f1b2  = (const float*)d_in[4];
    const float* f1w3  = (const float*)d_in[5];
    const float* f1b3  = (const float*)d_in[6];
    const float* f2w1  = (const float*)d_in[7];
    const float* f2b1  = (const float*)d_in[8];
    const float* f2w2  = (const float*)d_in[9];
    const float* f2b2  = (const float*)d_in[10];
    const float* f2w3  = (const float*)d_in[11];
    const float* f2b3  = (const float*)d_in[12];
    float* out = (float*)d_out;

    const int B = in_sizes[0] / 128;

    float *h1, *h2, *pa, *up, *ld;
    cudaGetSymbolAddress((void**)&h1, g_h1);
    cudaGetSymbolAddress((void**)&h2, g_h2);
    cudaGetSymbolAddress((void**)&pa, g_params);
    cudaGetSymbolAddress((void**)&up, g_up);
    cudaGetSymbolAddress((void**)&ld, g_ld);

    const dim3 blk(256);
    const int MB = B / 128;  // M tiles

    // ---- FCNN1 on lower half of x ----
    sgemm_bias<1><<<dim3(HD / 64, MB), blk>>>(x, 128, f1w1, f1b1, h1, B, HD, 64);
    sgemm_bias<1><<<dim3(HD / 64, MB), blk>>>(h1, HD, f1w2, f1b2, h2, B, HD, HD);
    sgemm_bias<0><<<dim3(PDIM / 64, MB), blk>>>(h2, HD, f1w3, f1b3, pa, B, PDIM, HD);

    // ---- RQS on upper half ----
    rqs_kernel<<<B, 64>>>(x, pa, up, out, ld, 0, B);

    // ---- FCNN2 on transformed upper ----
    sgemm_bias<1><<<dim3(HD / 64, MB), blk>>>(up, 64, f2w1, f2b1, h1, B, HD, 64);
    sgemm_bias<1><<<dim3(HD / 64, MB), blk>>>(h1, HD, f2w2, f2b2, h2, B, HD, HD);
    sgemm_bias<0><<<dim3(PDIM / 64, MB), blk>>>(h2, HD, f2w3, f2b3, pa, B, PDIM, HD);

    // ---- RQS on lower half + final logdet ----
    rqs_kernel<<<B, 64>>>(x, pa, nullptr, out, ld, 1, B);
}